// round 1
// baseline (speedup 1.0000x reference)
#include <cuda_runtime.h>
#include <math.h>

#define BB 8
#define SS 1024
#define HH 8
#define EE 64
#define NTOK (BB*SS)       // 8192 tokens
#define NCIRC (NTOK*HH)    // 65536 circuits

// Scratch (device globals — no allocation allowed)
__device__ float g_proj[NTOK * EE];   // 2 MB
__device__ float g_attn[NTOK * EE];   // 2 MB

// ---------------------------------------------------------------------------
// Kernel 1: quantum heads -> closed form prefix products of cos(x+theta)
//   proj[w] = prod_{i=0..w} c_i   (w = 1..7)
//   proj[0] = prod_{i=1..7} c_i
// ---------------------------------------------------------------------------
__global__ __launch_bounds__(256) void proj_kernel(const float* __restrict__ x,
                                                   const float* __restrict__ theta) {
    int idx = blockIdx.x * blockDim.x + threadIdx.x;
    if (idx >= NCIRC) return;

    const float4* x4 = (const float4*)x;
    float4 x0 = x4[idx * 2 + 0];
    float4 x1 = x4[idx * 2 + 1];

    float a[8] = {x0.x, x0.y, x0.z, x0.w, x1.x, x1.y, x1.z, x1.w};
    float c[8];
#pragma unroll
    for (int i = 0; i < 8; i++) c[i] = cosf(a[i] + __ldg(&theta[i]));

    float p[8];
    // prefix products including c0
    p[1] = c[0] * c[1];
#pragma unroll
    for (int w = 2; w < 8; w++) p[w] = p[w - 1] * c[w];
    // wire 0: product of c1..c7 (avoid division; recompute suffix)
    float q = c[1];
#pragma unroll
    for (int i = 2; i < 8; i++) q *= c[i];
    p[0] = q;

    float4* o4 = (float4*)g_proj;
    o4[idx * 2 + 0] = make_float4(p[0], p[1], p[2], p[3]);
    o4[idx * 2 + 1] = make_float4(p[4], p[5], p[6], p[7]);
}

// ---------------------------------------------------------------------------
// Kernel 2: self-attention per (b,h), d_k = 8, full K/V tile in smem.
// Scores are bounded (|dot*scale| <= 2.83) so single-pass exp-sum is stable.
// Grid: (B*H, S/QBLK), block: QBLK threads, one query per thread.
// ---------------------------------------------------------------------------
#define QBLK 128

__global__ __launch_bounds__(QBLK) void attn_kernel() {
    __shared__ float4 sk[SS * 2];   // 1024 keys x 8 floats = 32 KB

    int bh = blockIdx.x;
    int b  = bh >> 3;
    int h  = bh & 7;

    // load K (= V = Q source) tile: proj[(b*S+s)*64 + h*8 ..], as 2 float4 per key
    const float4* base = (const float4*)g_proj;
    for (int s = threadIdx.x; s < SS; s += QBLK) {
        int o = (b * SS + s) * 16 + h * 2;
        sk[s * 2 + 0] = base[o + 0];
        sk[s * 2 + 1] = base[o + 1];
    }
    __syncthreads();

    int q = blockIdx.y * QBLK + threadIdx.x;
    float4 q0 = sk[q * 2 + 0];
    float4 q1 = sk[q * 2 + 1];

    // fold softmax scale into exp2: exp(dot/sqrt(8)) = exp2(dot * log2e/sqrt8)
    const float kexp = 1.4426950408889634f * 0.35355339059327373f;

    float d0 = 0.f, d1 = 0.f, d2 = 0.f, d3 = 0.f, d4 = 0.f, d5 = 0.f, d6 = 0.f, d7 = 0.f;
    float denom = 0.f;

#pragma unroll 4
    for (int s = 0; s < SS; s++) {
        float4 k0 = sk[s * 2 + 0];   // warp-uniform -> smem broadcast
        float4 k1 = sk[s * 2 + 1];
        float dot = q0.x * k0.x + q0.y * k0.y + q0.z * k0.z + q0.w * k0.w
                  + q1.x * k1.x + q1.y * k1.y + q1.z * k1.z + q1.w * k1.w;
        float w = exp2f(dot * kexp);
        denom += w;
        d0 += w * k0.x; d1 += w * k0.y; d2 += w * k0.z; d3 += w * k0.w;
        d4 += w * k1.x; d5 += w * k1.y; d6 += w * k1.z; d7 += w * k1.w;
    }

    float inv = __frcp_rn(denom);
    float4* o4 = (float4*)g_attn;
    int o = (b * SS + q) * 16 + h * 2;
    o4[o + 0] = make_float4(d0 * inv, d1 * inv, d2 * inv, d3 * inv);
    o4[o + 1] = make_float4(d4 * inv, d5 * inv, d6 * inv, d7 * inv);
}

// ---------------------------------------------------------------------------
// Kernel 3: out[token, e] = sum_k attn[token, k] * W[e, k]
// W transposed into smem so the e-indexed read is conflict-free.
// Block: 256 threads = 4 tokens x 64 outputs.
// ---------------------------------------------------------------------------
__global__ __launch_bounds__(256) void combine_kernel(const float* __restrict__ W,
                                                      float* __restrict__ out) {
    __shared__ float Wt[EE * EE];   // Wt[k*64+e] = W[e*64+k], 16 KB
    for (int i = threadIdx.x; i < EE * EE; i += 256) {
        int e = i >> 6, k = i & 63;
        Wt[k * EE + e] = W[i];
    }
    __syncthreads();

    int lt = threadIdx.x >> 6;        // 0..3
    int e  = threadIdx.x & 63;
    int token = blockIdx.x * 4 + lt;

    const float* row = g_attn + token * EE;   // warp-uniform loads -> L1 broadcast
    float acc = 0.f;
#pragma unroll
    for (int k = 0; k < EE; k++) acc = fmaf(__ldg(&row[k]), Wt[k * EE + e], acc);
    out[token * EE + e] = acc;
}

// ---------------------------------------------------------------------------
extern "C" void kernel_launch(void* const* d_in, const int* in_sizes, int n_in,
                              void* d_out, int out_size) {
    const float* x      = (const float*)d_in[0];   // [8,1024,64]
    const float* theta  = (const float*)d_in[1];   // [8]
    const float* Wc     = (const float*)d_in[2];   // [64,64]
    float* out          = (float*)d_out;           // [8,1024,64]

    proj_kernel<<<NCIRC / 256, 256>>>(x, theta);

    dim3 agrid(BB * HH, SS / QBLK);
    attn_kernel<<<agrid, QBLK>>>();

    combine_kernel<<<NTOK / 4, 256>>>(Wc, out);
}

// round 2
// speedup vs baseline: 1.0020x; 1.0020x over previous
#include <cuda_runtime.h>
#include <math.h>

#define BB 8
#define SS 1024
#define HH 8
#define EE 64
#define NTOK (BB*SS)       // 8192 tokens
#define NCIRC (NTOK*HH)    // 65536 circuits

typedef unsigned long long u64;

// Scratch (device globals — no allocation allowed)
__device__ __align__(16) float g_proj[NTOK * EE];   // 2 MB
__device__ __align__(16) float g_attn[NTOK * EE];   // 2 MB

// ---------------------------------------------------------------------------
// f32x2 packed-math helpers (FFMA2 / packed ops, PTX-only on sm_103a)
// ---------------------------------------------------------------------------
__device__ __forceinline__ u64 pk2(float lo, float hi) {
    u64 r; asm("mov.b64 %0, {%1, %2};" : "=l"(r) : "f"(lo), "f"(hi)); return r;
}
__device__ __forceinline__ void upk2(u64 v, float& lo, float& hi) {
    asm("mov.b64 {%0, %1}, %2;" : "=f"(lo), "=f"(hi) : "l"(v));
}
__device__ __forceinline__ u64 pfma(u64 a, u64 b, u64 c) {
    u64 d; asm("fma.rn.f32x2 %0, %1, %2, %3;" : "=l"(d) : "l"(a), "l"(b), "l"(c)); return d;
}
__device__ __forceinline__ u64 pmul(u64 a, u64 b) {
    u64 d; asm("mul.rn.f32x2 %0, %1, %2;" : "=l"(d) : "l"(a), "l"(b)); return d;
}
__device__ __forceinline__ u64 padd(u64 a, u64 b) {
    u64 d; asm("add.rn.f32x2 %0, %1, %2;" : "=l"(d) : "l"(a), "l"(b)); return d;
}
__device__ __forceinline__ float ex2(float x) {
    float y; asm("ex2.approx.f32 %0, %1;" : "=f"(y) : "f"(x)); return y;
}

// ---------------------------------------------------------------------------
// Kernel 1: quantum heads -> closed form prefix products of cos(x+theta)
//   proj[w] = prod_{i=0..w} c_i   (w = 1..7)
//   proj[0] = prod_{i=1..7} c_i
// __cosf (MUFU.COS): abs err ~1e-6 at |arg|<~6; 8-term products stay ~1e-5,
// far inside the 1e-3 rel_err budget.
// ---------------------------------------------------------------------------
__global__ __launch_bounds__(256) void proj_kernel(const float* __restrict__ x,
                                                   const float* __restrict__ theta) {
    int idx = blockIdx.x * blockDim.x + threadIdx.x;
    if (idx >= NCIRC) return;

    const float4* x4 = (const float4*)x;
    float4 x0 = x4[idx * 2 + 0];
    float4 x1 = x4[idx * 2 + 1];

    float a[8] = {x0.x, x0.y, x0.z, x0.w, x1.x, x1.y, x1.z, x1.w};
    float c[8];
#pragma unroll
    for (int i = 0; i < 8; i++) c[i] = __cosf(a[i] + __ldg(&theta[i]));

    float p[8];
    p[1] = c[0] * c[1];
#pragma unroll
    for (int w = 2; w < 8; w++) p[w] = p[w - 1] * c[w];
    float q = c[1];
#pragma unroll
    for (int i = 2; i < 8; i++) q *= c[i];
    p[0] = q;

    float4* o4 = (float4*)g_proj;
    o4[idx * 2 + 0] = make_float4(p[0], p[1], p[2], p[3]);
    o4[idx * 2 + 1] = make_float4(p[4], p[5], p[6], p[7]);
}

// ---------------------------------------------------------------------------
// Kernel 2: self-attention per (b,h), d_k = 8, full K/V tile in smem.
// All math packed f32x2 along the feature dim: k arrives pre-packed from
// LDS.128 ((k0,k1),(k2,k3) per ulonglong2), q pre-scaled by softmax*log2e.
// Scores bounded (|dot*scale*log2e| <= 4.1) -> raw ex2, no max subtraction.
// ---------------------------------------------------------------------------
#define QBLK 128

__global__ __launch_bounds__(QBLK) void attn_kernel() {
    __shared__ ulonglong2 sk[SS * 2];   // 1024 keys x 8 floats = 32 KB

    int bh = blockIdx.x;
    int b  = bh >> 3;
    int h  = bh & 7;

    // load K (= V = Q source) tile
    const ulonglong2* base = (const ulonglong2*)g_proj;
    for (int s = threadIdx.x; s < SS; s += QBLK) {
        int o = (b * SS + s) * 16 + h * 2;   // in float4/ulonglong2 units
        sk[s * 2 + 0] = base[o + 0];
        sk[s * 2 + 1] = base[o + 1];
    }
    __syncthreads();

    int q = blockIdx.y * QBLK + threadIdx.x;

    // q pre-scaled by log2(e)/sqrt(8): exp(dot/sqrt8) = exp2(dotscaled)
    const float kexp = 1.4426950408889634f * 0.35355339059327373f;
    const u64 KK = pk2(kexp, kexp);
    ulonglong2 Qa = sk[q * 2 + 0];
    ulonglong2 Qb = sk[q * 2 + 1];
    u64 q01 = pmul(Qa.x, KK), q23 = pmul(Qa.y, KK);
    u64 q45 = pmul(Qb.x, KK), q67 = pmul(Qb.y, KK);

    u64 d01 = 0, d23 = 0, d45 = 0, d67 = 0;
    float denom = 0.f;

#pragma unroll 4
    for (int s = 0; s < SS; s++) {
        ulonglong2 A = sk[s * 2 + 0];   // (k0,k1),(k2,k3) -- warp-uniform broadcast
        ulonglong2 B = sk[s * 2 + 1];   // (k4,k5),(k6,k7)
        u64 t0 = pmul(q01, A.x);
        u64 t1 = pmul(q45, B.x);
        t0 = pfma(q23, A.y, t0);
        t1 = pfma(q67, B.y, t1);
        t0 = padd(t0, t1);
        float lo, hi; upk2(t0, lo, hi);
        float w = ex2(lo + hi);
        denom += w;
        u64 ww = pk2(w, w);
        d01 = pfma(ww, A.x, d01);
        d23 = pfma(ww, A.y, d23);
        d45 = pfma(ww, B.x, d45);
        d67 = pfma(ww, B.y, d67);
    }

    float inv = __frcp_rn(denom);
    u64 ii = pk2(inv, inv);
    ulonglong2* o2 = (ulonglong2*)g_attn;
    int o = (b * SS + q) * 16 + h * 2;
    ulonglong2 r0, r1;
    r0.x = pmul(d01, ii); r0.y = pmul(d23, ii);
    r1.x = pmul(d45, ii); r1.y = pmul(d67, ii);
    o2[o + 0] = r0;
    o2[o + 1] = r1;
}

// ---------------------------------------------------------------------------
// Kernel 3: out[token, e] = sum_k attn[token, k] * W[e, k]
// W transposed into smem so the e-indexed read is conflict-free.
// ---------------------------------------------------------------------------
__global__ __launch_bounds__(256) void combine_kernel(const float* __restrict__ W,
                                                      float* __restrict__ out) {
    __shared__ float Wt[EE * EE];   // Wt[k*64+e] = W[e*64+k], 16 KB
    for (int i = threadIdx.x; i < EE * EE; i += 256) {
        int e = i >> 6, k = i & 63;
        Wt[k * EE + e] = W[i];
    }
    __syncthreads();

    int lt = threadIdx.x >> 6;        // 0..3
    int e  = threadIdx.x & 63;
    int token = blockIdx.x * 4 + lt;

    const float* row = g_attn + token * EE;   // warp-uniform loads -> L1 broadcast
    float acc = 0.f;
#pragma unroll
    for (int k = 0; k < EE; k++) acc = fmaf(__ldg(&row[k]), Wt[k * EE + e], acc);
    out[token * EE + e] = acc;
}

// ---------------------------------------------------------------------------
extern "C" void kernel_launch(void* const* d_in, const int* in_sizes, int n_in,
                              void* d_out, int out_size) {
    const float* x      = (const float*)d_in[0];   // [8,1024,64]
    const float* theta  = (const float*)d_in[1];   // [8]
    const float* Wc     = (const float*)d_in[2];   // [64,64]
    float* out          = (float*)d_out;           // [8,1024,64]

    proj_kernel<<<NCIRC / 256, 256>>>(x, theta);

    dim3 agrid(BB * HH, SS / QBLK);
    attn_kernel<<<agrid, QBLK>>>();

    combine_kernel<<<NTOK / 4, 256>>>(Wc, out);
}

// round 3
// speedup vs baseline: 1.1946x; 1.1922x over previous
#include <cuda_runtime.h>
#include <math.h>

#define BB 8
#define SS 1024
#define HH 8
#define EE 64
#define NTOK (BB*SS)       // 8192 tokens
#define NCIRC (NTOK*HH)    // 65536 circuits

typedef unsigned long long u64;

// Scratch (device globals — no allocation allowed)
__device__ __align__(16) float g_proj[NTOK * EE];   // 2 MB
__device__ __align__(16) float g_attn[NTOK * EE];   // 2 MB

// ---------------------------------------------------------------------------
// f32x2 packed-math helpers (FFMA2 / packed ops, PTX-only on sm_103a)
// ---------------------------------------------------------------------------
__device__ __forceinline__ u64 pk2(float lo, float hi) {
    u64 r; asm("mov.b64 %0, {%1, %2};" : "=l"(r) : "f"(lo), "f"(hi)); return r;
}
__device__ __forceinline__ void upk2(u64 v, float& lo, float& hi) {
    asm("mov.b64 {%0, %1}, %2;" : "=f"(lo), "=f"(hi) : "l"(v));
}
__device__ __forceinline__ u64 pfma(u64 a, u64 b, u64 c) {
    u64 d; asm("fma.rn.f32x2 %0, %1, %2, %3;" : "=l"(d) : "l"(a), "l"(b), "l"(c)); return d;
}
__device__ __forceinline__ u64 pmul(u64 a, u64 b) {
    u64 d; asm("mul.rn.f32x2 %0, %1, %2;" : "=l"(d) : "l"(a), "l"(b)); return d;
}
__device__ __forceinline__ u64 padd(u64 a, u64 b) {
    u64 d; asm("add.rn.f32x2 %0, %1, %2;" : "=l"(d) : "l"(a), "l"(b)); return d;
}
__device__ __forceinline__ float ex2(float x) {
    float y; asm("ex2.approx.f32 %0, %1;" : "=f"(y) : "f"(x)); return y;
}

// ---------------------------------------------------------------------------
// Kernel 1: quantum heads -> closed form prefix products of cos(x+theta)
// ---------------------------------------------------------------------------
__global__ __launch_bounds__(256) void proj_kernel(const float* __restrict__ x,
                                                   const float* __restrict__ theta) {
    int idx = blockIdx.x * blockDim.x + threadIdx.x;
    if (idx >= NCIRC) return;

    const float4* x4 = (const float4*)x;
    float4 x0 = x4[idx * 2 + 0];
    float4 x1 = x4[idx * 2 + 1];

    float a[8] = {x0.x, x0.y, x0.z, x0.w, x1.x, x1.y, x1.z, x1.w};
    float c[8];
#pragma unroll
    for (int i = 0; i < 8; i++) c[i] = __cosf(a[i] + __ldg(&theta[i]));

    float p[8];
    p[1] = c[0] * c[1];
#pragma unroll
    for (int w = 2; w < 8; w++) p[w] = p[w - 1] * c[w];
    float q = c[1];
#pragma unroll
    for (int i = 2; i < 8; i++) q *= c[i];
    p[0] = q;

    float4* o4 = (float4*)g_proj;
    o4[idx * 2 + 0] = make_float4(p[0], p[1], p[2], p[3]);
    o4[idx * 2 + 1] = make_float4(p[4], p[5], p[6], p[7]);
}

// ---------------------------------------------------------------------------
// Kernel 2: attention, split-K over 4 slices for occupancy.
// Block = 256 threads = QBLK(64) queries x SLICES(4) key-slices.
// Each thread: 256 keys, packed f32x2 math. Partials reduced via smem.
// Warps have uniform slice -> sk reads stay warp-uniform broadcasts.
// ---------------------------------------------------------------------------
#define QBLK 64
#define SLICES 4
#define SPT (SS / SLICES)   // 256 keys per thread

__global__ __launch_bounds__(256, 4) void attn_kernel() {
    __shared__ ulonglong2 sk[SS * 2];                 // 32 KB: 1024 keys x 8 f32
    __shared__ float part[9][SLICES][QBLK];           // 9 KB partials

    int bh = blockIdx.x;
    int b  = bh >> 3;
    int h  = bh & 7;

    // load K (= V = Q source) tile
    const ulonglong2* base = (const ulonglong2*)g_proj;
    for (int s = threadIdx.x; s < SS; s += 256) {
        int o = (b * SS + s) * 16 + h * 2;   // 16B units per token row
        sk[s * 2 + 0] = base[o + 0];
        sk[s * 2 + 1] = base[o + 1];
    }
    __syncthreads();

    int qlocal = threadIdx.x & (QBLK - 1);
    int slice  = threadIdx.x >> 6;           // warp-uniform
    int q = blockIdx.y * QBLK + qlocal;

    // q pre-scaled by log2(e)/sqrt(8)
    const float kexp = 1.4426950408889634f * 0.35355339059327373f;
    const u64 KK = pk2(kexp, kexp);
    ulonglong2 Qa = sk[q * 2 + 0];
    ulonglong2 Qb = sk[q * 2 + 1];
    u64 q01 = pmul(Qa.x, KK), q23 = pmul(Qa.y, KK);
    u64 q45 = pmul(Qb.x, KK), q67 = pmul(Qb.y, KK);

    u64 d01 = 0, d23 = 0, d45 = 0, d67 = 0;
    float denom = 0.f;

    int s0 = slice * SPT;
#pragma unroll 4
    for (int i = 0; i < SPT; i++) {
        int s = s0 + i;
        ulonglong2 A = sk[s * 2 + 0];   // warp-uniform -> broadcast
        ulonglong2 B = sk[s * 2 + 1];
        u64 t0 = pmul(q01, A.x);
        u64 t1 = pmul(q45, B.x);
        t0 = pfma(q23, A.y, t0);
        t1 = pfma(q67, B.y, t1);
        t0 = padd(t0, t1);
        float lo, hi; upk2(t0, lo, hi);
        float w = ex2(lo + hi);
        denom += w;
        u64 ww = pk2(w, w);
        d01 = pfma(ww, A.x, d01);
        d23 = pfma(ww, A.y, d23);
        d45 = pfma(ww, B.x, d45);
        d67 = pfma(ww, B.y, d67);
    }

    // dump partials (stride-1 in qlocal -> conflict-free)
    {
        float v0, v1; upk2(d01, v0, v1);
        part[0][slice][qlocal] = v0; part[1][slice][qlocal] = v1;
        upk2(d23, v0, v1);
        part[2][slice][qlocal] = v0; part[3][slice][qlocal] = v1;
        upk2(d45, v0, v1);
        part[4][slice][qlocal] = v0; part[5][slice][qlocal] = v1;
        upk2(d67, v0, v1);
        part[6][slice][qlocal] = v0; part[7][slice][qlocal] = v1;
        part[8][slice][qlocal] = denom;
    }
    __syncthreads();

    if (threadIdx.x < QBLK) {
        int t = threadIdx.x;
        float acc[9];
#pragma unroll
        for (int j = 0; j < 9; j++)
            acc[j] = (part[j][0][t] + part[j][1][t]) + (part[j][2][t] + part[j][3][t]);

        float inv = __frcp_rn(acc[8]);
        ulonglong2* o2 = (ulonglong2*)g_attn;
        int o = (b * SS + blockIdx.y * QBLK + t) * 16 + h * 2;
        ulonglong2 r0, r1;
        r0.x = pk2(acc[0] * inv, acc[1] * inv);
        r0.y = pk2(acc[2] * inv, acc[3] * inv);
        r1.x = pk2(acc[4] * inv, acc[5] * inv);
        r1.y = pk2(acc[6] * inv, acc[7] * inv);
        o2[o + 0] = r0;
        o2[o + 1] = r1;
    }
}

// ---------------------------------------------------------------------------
// Kernel 3: out[token, e] = sum_k attn[token, k] * W[e, k], packed f32x2.
// Block 256 = 8 tokens x 32 e-pairs; Wt transposed in smem, read as u64 pairs.
// ---------------------------------------------------------------------------
__global__ __launch_bounds__(256) void combine_kernel(const float* __restrict__ W,
                                                      float* __restrict__ out) {
    __shared__ float Wt[EE * EE];   // Wt[k*64+e] = W[e*64+k], 16 KB
    for (int i = threadIdx.x; i < EE * EE; i += 256) {
        int e = i >> 6, k = i & 63;
        Wt[k * EE + e] = W[i];
    }
    __syncthreads();

    int token = blockIdx.x * 8 + (threadIdx.x >> 5);
    int p = threadIdx.x & 31;                 // e-pair index: outputs 2p, 2p+1
    const u64* Wt2 = (const u64*)Wt;          // Wt2[k*32+p] = (Wt[k][2p], Wt[k][2p+1])
    const float* row = g_attn + token * EE;   // warp-uniform -> L1 broadcast

    u64 acc = 0;
#pragma unroll
    for (int k = 0; k < EE; k++) {
        float r = __ldg(&row[k]);
        acc = pfma(pk2(r, r), Wt2[k * 32 + p], acc);
    }
    float lo, hi; upk2(acc, lo, hi);
    ((float2*)out)[token * 32 + p] = make_float2(lo, hi);
}

// ---------------------------------------------------------------------------
extern "C" void kernel_launch(void* const* d_in, const int* in_sizes, int n_in,
                              void* d_out, int out_size) {
    const float* x      = (const float*)d_in[0];   // [8,1024,64]
    const float* theta  = (const float*)d_in[1];   // [8]
    const float* Wc     = (const float*)d_in[2];   // [64,64]
    float* out          = (float*)d_out;           // [8,1024,64]

    proj_kernel<<<NCIRC / 256, 256>>>(x, theta);

    dim3 agrid(BB * HH, SS / QBLK);
    attn_kernel<<<agrid, 256>>>();

    combine_kernel<<<NTOK / 8, 256>>>(Wc, out);
}

// round 5
// speedup vs baseline: 1.4703x; 1.2308x over previous
#include <cuda_runtime.h>
#include <math.h>

#define BB 8
#define SS 1024
#define HH 8
#define EE 64
#define NTOK (BB*SS)       // 8192 tokens
#define NCIRC (NTOK*HH)    // 65536 circuits
#define NPAIR (SS/2)       // 512 key pairs per (b,h)

typedef unsigned long long u64;

// Scratch (device globals — no allocation allowed)
// g_projT: key-pair-interleaved proj, (b,h)-major:
//   g_projT[((b*8+h)*512 + p)*8 + i] = ( proj[b,2p,h,i], proj[b,2p+1,h,i] )
__device__ __align__(16) u64   g_projT[BB * HH * NPAIR * 8];  // 2 MB
__device__ __align__(16) float g_attn[NTOK * EE];             // 2 MB

// ---------------------------------------------------------------------------
// f32x2 packed-math helpers (FFMA2 etc., PTX-only on sm_103a)
// ---------------------------------------------------------------------------
__device__ __forceinline__ u64 pk2(float lo, float hi) {
    u64 r; asm("mov.b64 %0, {%1, %2};" : "=l"(r) : "f"(lo), "f"(hi)); return r;
}
__device__ __forceinline__ void upk2(u64 v, float& lo, float& hi) {
    asm("mov.b64 {%0, %1}, %2;" : "=f"(lo), "=f"(hi) : "l"(v));
}
__device__ __forceinline__ u64 pfma(u64 a, u64 b, u64 c) {
    u64 d; asm("fma.rn.f32x2 %0, %1, %2, %3;" : "=l"(d) : "l"(a), "l"(b), "l"(c)); return d;
}
__device__ __forceinline__ u64 pmul(u64 a, u64 b) {
    u64 d; asm("mul.rn.f32x2 %0, %1, %2;" : "=l"(d) : "l"(a), "l"(b)); return d;
}
__device__ __forceinline__ u64 padd(u64 a, u64 b) {
    u64 d; asm("add.rn.f32x2 %0, %1, %2;" : "=l"(d) : "l"(a), "l"(b)); return d;
}
__device__ __forceinline__ float ex2(float x) {
    float y; asm("ex2.approx.f32 %0, %1;" : "=f"(y) : "f"(x)); return y;
}

// ---------------------------------------------------------------------------
// Kernel 1: quantum heads -> prefix products of cos(x+theta), written in
// key-pair-interleaved (b,h)-major layout for the attention kernel.
// Circuit c = (b*1024+s)*8 + h; lanes c and c^8 are tokens (s, s^1) same h.
// ---------------------------------------------------------------------------
__global__ __launch_bounds__(256) void proj_kernel(const float* __restrict__ x,
                                                   const float* __restrict__ theta) {
    int c = blockIdx.x * 256 + threadIdx.x;   // < NCIRC (exact)
    int h = c & 7;
    int token = c >> 3;
    int b = token >> 10;
    int s = token & 1023;

    const float4* x4 = (const float4*)x;
    float4 x0 = x4[token * 16 + h * 2 + 0];
    float4 x1 = x4[token * 16 + h * 2 + 1];

    float a[8] = {x0.x, x0.y, x0.z, x0.w, x1.x, x1.y, x1.z, x1.w};
    float cc[8];
#pragma unroll
    for (int i = 0; i < 8; i++) cc[i] = __cosf(a[i] + __ldg(&theta[i]));

    float p[8];
    p[1] = cc[0] * cc[1];
#pragma unroll
    for (int w = 2; w < 8; w++) p[w] = p[w - 1] * cc[w];
    float qq = cc[1];
#pragma unroll
    for (int i = 2; i < 8; i++) qq *= cc[i];
    p[0] = qq;

    // pair with neighbor token (s^1): lane xor 8 (bit 3 of tid = s bit 0)
    u64 outw[8];
#pragma unroll
    for (int i = 0; i < 8; i++) {
        float pp = __shfl_xor_sync(0xffffffffu, p[i], 8);
        outw[i] = pk2(p[i], pp);   // valid for even-s lanes: (k_s[i], k_{s+1}[i])
    }
    if ((s & 1) == 0) {
        ulonglong2* dst = (ulonglong2*)(g_projT + (size_t)((b * 8 + h) * 512 + (s >> 1)) * 8);
        ulonglong2 v0; v0.x = outw[0]; v0.y = outw[1];
        ulonglong2 v1; v1.x = outw[2]; v1.y = outw[3];
        ulonglong2 v2; v2.x = outw[4]; v2.y = outw[5];
        ulonglong2 v3; v3.x = outw[6]; v3.y = outw[7];
        dst[0] = v0; dst[1] = v1; dst[2] = v2; dst[3] = v3;
    }
}

// ---------------------------------------------------------------------------
// Kernel 2: attention, key-pair-packed f32x2 + split-K over 4 slices.
// Block = 256 = QBLK(64) queries x SLICES(4). Each thread: 128 key-pairs.
// Per pair: 18 FMA-pipe ops for 2 keys (no cross-lane score reduction;
// V-accumulators packed over (even,odd) keys, folded at the end).
// ---------------------------------------------------------------------------
#define QBLK 64
#define SLICES 4
#define PPT (NPAIR / SLICES)   // 128 pairs per thread

__global__ __launch_bounds__(256, 4) void attn_kernel() {
    __shared__ u64 skp[NPAIR * 8];                 // 32 KB interleaved tile
    __shared__ float part[9][SLICES][QBLK];        // 9 KB partials

    int bh = blockIdx.x;
    int b  = bh >> 3;
    int h  = bh & 7;

    // contiguous, fully-coalesced tile load (4096 u64 = 2048 ulonglong2)
    const ulonglong2* src = (const ulonglong2*)(g_projT + (size_t)bh * NPAIR * 8);
    ulonglong2* dst2 = (ulonglong2*)skp;
    for (int i = threadIdx.x; i < NPAIR * 4; i += 256) dst2[i] = src[i];
    __syncthreads();

    int qlocal = threadIdx.x & (QBLK - 1);
    int slice  = threadIdx.x >> 6;              // warp-uniform
    int q = blockIdx.y * QBLK + qlocal;

    // q features live in lane (q&1) of pair q>>1; pre-scale by log2e/sqrt(8)
    const float kexp = 1.4426950408889634f * 0.35355339059327373f;
    const float* skf = (const float*)skp;
    u64 qd[8];
#pragma unroll
    for (int i = 0; i < 8; i++) {
        float v = skf[(((q >> 1) * 8 + i) << 1) + (q & 1)] * kexp;
        qd[i] = pk2(v, v);
    }

    u64 dP0 = 0, dP1 = 0, dP2 = 0, dP3 = 0, dP4 = 0, dP5 = 0, dP6 = 0, dP7 = 0;
    u64 denomP = 0;

    int p0 = slice * PPT;
#pragma unroll 2
    for (int pp = p0; pp < p0 + PPT; pp++) {
        const ulonglong2* kp = (const ulonglong2*)&skp[pp * 8];  // warp-uniform bcast
        ulonglong2 kA = kp[0];   // (k_e[0],k_o[0]) , (k_e[1],k_o[1])
        ulonglong2 kB = kp[1];
        ulonglong2 kC = kp[2];
        ulonglong2 kD = kp[3];
        u64 c1 = pmul(qd[0], kA.x);
        c1 = pfma(qd[1], kA.y, c1);
        c1 = pfma(qd[2], kB.x, c1);
        c1 = pfma(qd[3], kB.y, c1);
        u64 c2 = pmul(qd[4], kC.x);
        c2 = pfma(qd[5], kC.y, c2);
        c2 = pfma(qd[6], kD.x, c2);
        c2 = pfma(qd[7], kD.y, c2);
        u64 dotP = padd(c1, c2);            // (score_even, score_odd) pre-scaled
        float e0, e1; upk2(dotP, e0, e1);
        u64 w01 = pk2(ex2(e0), ex2(e1));
        denomP = padd(denomP, w01);
        dP0 = pfma(w01, kA.x, dP0);
        dP1 = pfma(w01, kA.y, dP1);
        dP2 = pfma(w01, kB.x, dP2);
        dP3 = pfma(w01, kB.y, dP3);
        dP4 = pfma(w01, kC.x, dP4);
        dP5 = pfma(w01, kC.y, dP5);
        dP6 = pfma(w01, kD.x, dP6);
        dP7 = pfma(w01, kD.y, dP7);
    }

    // fold (even,odd) lanes, dump partials (stride-1 in qlocal -> conflict-free)
    {
        float lo, hi;
        upk2(dP0, lo, hi); part[0][slice][qlocal] = lo + hi;
        upk2(dP1, lo, hi); part[1][slice][qlocal] = lo + hi;
        upk2(dP2, lo, hi); part[2][slice][qlocal] = lo + hi;
        upk2(dP3, lo, hi); part[3][slice][qlocal] = lo + hi;
        upk2(dP4, lo, hi); part[4][slice][qlocal] = lo + hi;
        upk2(dP5, lo, hi); part[5][slice][qlocal] = lo + hi;
        upk2(dP6, lo, hi); part[6][slice][qlocal] = lo + hi;
        upk2(dP7, lo, hi); part[7][slice][qlocal] = lo + hi;
        upk2(denomP, lo, hi); part[8][slice][qlocal] = lo + hi;
    }
    __syncthreads();

    if (threadIdx.x < QBLK) {
        int t = threadIdx.x;
        float acc[9];
#pragma unroll
        for (int j = 0; j < 9; j++)
            acc[j] = (part[j][0][t] + part[j][1][t]) + (part[j][2][t] + part[j][3][t]);

        float inv = __frcp_rn(acc[8]);
        ulonglong2* o2 = (ulonglong2*)g_attn;
        int o = (b * SS + blockIdx.y * QBLK + t) * 16 + h * 2;  // 16 u2 per token
        ulonglong2 r0, r1;
        r0.x = pk2(acc[0] * inv, acc[1] * inv);
        r0.y = pk2(acc[2] * inv, acc[3] * inv);
        r1.x = pk2(acc[4] * inv, acc[5] * inv);
        r1.y = pk2(acc[6] * inv, acc[7] * inv);
        o2[o + 0] = r0;
        o2[o + 1] = r1;
    }
}

// ---------------------------------------------------------------------------
// Kernel 3: out[token, e] = sum_k attn[token, k] * W[e, k]
// Register-tiled: 256 CTAs x 256 thr; thread = 1 token x 8 output-pairs.
// Per k: 1 LDS.32 (padded, conflict-free) + 2 LDS.128 (wt pairs) + 4 FFMA2.
// ---------------------------------------------------------------------------
__global__ __launch_bounds__(256) void combine_kernel(const float* __restrict__ W,
                                                      float* __restrict__ out) {
    __shared__ float wt[EE * EE];        // wt[k*64+e] = W[e*64+k], 16 KB
    __shared__ float rows[32][68];       // 32 token rows, padded (+4)

    int tid = threadIdx.x;
    for (int i = tid; i < EE * EE; i += 256) {
        int e = i >> 6, k = i & 63;
        wt[k * EE + e] = W[i];
    }
    int token0 = blockIdx.x * 32;
    const float4* ga4 = (const float4*)g_attn + token0 * 16;
    for (int i = tid; i < 512; i += 256) {     // 32 tokens x 16 float4, coalesced
        int t = i >> 4, kg = i & 15;
        float4 v = ga4[i];
        rows[t][kg * 4 + 0] = v.x; rows[t][kg * 4 + 1] = v.y;
        rows[t][kg * 4 + 2] = v.z; rows[t][kg * 4 + 3] = v.w;
    }
    __syncthreads();

    int t  = tid >> 3;     // token 0..31
    int og = tid & 7;      // output group: e = og*8 .. og*8+7
    const ulonglong2* wt2 = (const ulonglong2*)wt;  // wt2[k*16 + j]

    u64 a0 = 0, a1 = 0, a2 = 0, a3 = 0;
#pragma unroll
    for (int k = 0; k < EE; k++) {
        float r = rows[t][k];
        u64 rr = pk2(r, r);
        ulonglong2 b0 = wt2[k * 16 + og * 2 + 0];
        ulonglong2 b1 = wt2[k * 16 + og * 2 + 1];
        a0 = pfma(rr, b0.x, a0);
        a1 = pfma(rr, b0.y, a1);
        a2 = pfma(rr, b1.x, a2);
        a3 = pfma(rr, b1.y, a3);
    }
    ulonglong2* o2 = (ulonglong2*)out;
    int token = token0 + t;
    // 16 ulonglong2 (= 64 floats) per token  [R4 bug: used *8]
    ulonglong2 r0; r0.x = a0; r0.y = a1;
    ulonglong2 r1; r1.x = a2; r1.y = a3;
    o2[token * 16 + og * 2 + 0] = r0;
    o2[token * 16 + og * 2 + 1] = r1;
}

// ---------------------------------------------------------------------------
extern "C" void kernel_launch(void* const* d_in, const int* in_sizes, int n_in,
                              void* d_out, int out_size) {
    const float* x      = (const float*)d_in[0];   // [8,1024,64]
    const float* theta  = (const float*)d_in[1];   // [8]
    const float* Wc     = (const float*)d_in[2];   // [64,64]
    float* out          = (float*)d_out;           // [8,1024,64]

    proj_kernel<<<NCIRC / 256, 256>>>(x, theta);

    dim3 agrid(BB * HH, SS / QBLK);
    attn_kernel<<<agrid, 256>>>();

    combine_kernel<<<NTOK / 32, 256>>>(Wc, out);
}

// round 7
// speedup vs baseline: 1.8189x; 1.2371x over previous
#include <cuda_runtime.h>
#include <cuda_bf16.h>

#define BB 8
#define SS 1024
#define HH 8
#define EE 64
#define NBH (BB*HH)
#define NTOK (BB*SS)

typedef unsigned long long u64;
typedef unsigned int u32;

__device__ __align__(16) float g_attn[NTOK * EE];   // 2 MB scratch

// ---------------------------------------------------------------------------
// helpers
// ---------------------------------------------------------------------------
__device__ __forceinline__ u64 pk2(float lo, float hi) {
    u64 r; asm("mov.b64 %0, {%1, %2};" : "=l"(r) : "f"(lo), "f"(hi)); return r;
}
__device__ __forceinline__ void upk2(u64 v, float& lo, float& hi) {
    asm("mov.b64 {%0, %1}, %2;" : "=f"(lo), "=f"(hi) : "l"(v));
}
__device__ __forceinline__ u64 pfma(u64 a, u64 b, u64 c) {
    u64 d; asm("fma.rn.f32x2 %0, %1, %2, %3;" : "=l"(d) : "l"(a), "l"(b), "l"(c)); return d;
}
__device__ __forceinline__ float ex2(float x) {
    float y; asm("ex2.approx.f32 %0, %1;" : "=f"(y) : "f"(x)); return y;
}
// pack two fp32 -> bf16x2; first arg lands in HIGH half, second in LOW half
__device__ __forceinline__ u32 cvtpk(float hi, float lo) {
    u32 r; asm("cvt.rn.bf16x2.f32 %0, %1, %2;" : "=r"(r) : "f"(hi), "f"(lo)); return r;
}

// m16n8k16 row.col bf16 MMA, fp32 accum (HMMA fallback path, sm_80+ PTX)
#define MMA_BF16(d0,d1,d2,d3, a0,a1,a2,a3, b0,b1, c0,c1,c2,c3) \
  asm volatile("mma.sync.aligned.m16n8k16.row.col.f32.bf16.bf16.f32 " \
    "{%0,%1,%2,%3}, {%4,%5,%6,%7}, {%8,%9}, {%10,%11,%12,%13};" \
    : "=f"(d0),"=f"(d1),"=f"(d2),"=f"(d3) \
    : "r"(a0),"r"(a1),"r"(a2),"r"(a3), "r"(b0),"r"(b1), \
      "f"(c0),"f"(c1),"f"(c2),"f"(c3))

// ---------------------------------------------------------------------------
// Fused proj + attention. CTA = (bh, qtile of 64 queries), 128 threads.
//
// Build: each thread computes cos-prefix products for 8 keys from x, splits
// each fp32 feature into bf16 hi+lo, stores two smem layouts:
//   skey  (key-major):  per key 8 u32 words [hi0..3 | lo0..3], words XOR'd
//                       with (key&4) -> conflict-free fragment loads
//   khiT/kloT (feat-major): word(f, s/2) = {hi[s][f], hi[s+1][f]}, row
//                       stride 516 u32 -> bank = 4f + tc, conflict-free
//
// Loop per warp (16 queries x 16 keys/iter):
//   scores: 2x2 MMAs, A=[qhi|qlo], B=[khi;khi] then [klo;klo] (exact fp32 dot)
//   w = ex2(score * log2e/sqrt(8)); fp32 denom accumulate
//   AV: D-fragments cvt-packed to bf16 == A-fragment of next MMA;
//       2 MMAs (khiT, kloT) accumulate out[16q x 8feat] in registers
// ---------------------------------------------------------------------------
#define ATTN_SMEM_BYTES 65792   // 8192 + 4128 + 4128 u32

__global__ __launch_bounds__(128) void attn_fused(const float* __restrict__ x,
                                                  const float* __restrict__ theta) {
    extern __shared__ __align__(16) u32 sm[];
    u32* skey = sm;                 // [1024*8]
    u32* khiT = sm + 8192;          // [8*516]
    u32* kloT = sm + 8192 + 4128;   // [8*516]

    int bh = blockIdx.x;
    int b = bh >> 3, h = bh & 7;
    int qt = blockIdx.y;
    int tid = threadIdx.x;

    float th[8];
#pragma unroll
    for (int i = 0; i < 8; i++) th[i] = __ldg(&theta[i]);

    // ---------------- build phase: keys tid*8 .. tid*8+7 ----------------
    const float* xb = x + (size_t)(b * SS) * 64 + h * 8;
    for (int pr = 0; pr < 4; pr++) {
        int s0 = tid * 8 + pr * 2;            // even key of the pair
        float hi[2][8], lo[2][8];
#pragma unroll
        for (int j = 0; j < 2; j++) {
            int s = s0 + j;
            const float4* xs = (const float4*)(xb + (size_t)s * 64);
            float4 v0 = xs[0], v1 = xs[1];
            float a[8] = {v0.x, v0.y, v0.z, v0.w, v1.x, v1.y, v1.z, v1.w};
            float c[8];
#pragma unroll
            for (int i = 0; i < 8; i++) c[i] = __cosf(a[i] + th[i]);
            float p[8];
            p[1] = c[0] * c[1];
#pragma unroll
            for (int w = 2; w < 8; w++) p[w] = p[w - 1] * c[w];
            float qq = c[1];
#pragma unroll
            for (int i = 2; i < 8; i++) qq *= c[i];
            p[0] = qq;
#pragma unroll
            for (int i = 0; i < 8; i++) {
                float hf = __bfloat162float(__float2bfloat16(p[i]));
                hi[j][i] = hf;
                lo[j][i] = p[i] - hf;
            }
            // key-major words: w in 0..3 = {hi[2w],hi[2w+1]}, 4..7 = lo pairs
            uint4 HW = make_uint4(cvtpk(hi[j][1], hi[j][0]), cvtpk(hi[j][3], hi[j][2]),
                                  cvtpk(hi[j][5], hi[j][4]), cvtpk(hi[j][7], hi[j][6]));
            uint4 LW = make_uint4(cvtpk(lo[j][1], lo[j][0]), cvtpk(lo[j][3], lo[j][2]),
                                  cvtpk(lo[j][5], lo[j][4]), cvtpk(lo[j][7], lo[j][6]));
            uint4* kp = (uint4*)(skey + s * 8);
            if (s & 4) { kp[0] = LW; kp[1] = HW; }   // word index XOR 4
            else       { kp[0] = HW; kp[1] = LW; }
        }
        int pw = s0 >> 1;
#pragma unroll
        for (int f = 0; f < 8; f++) {
            khiT[f * 516 + pw] = cvtpk(hi[1][f], hi[0][f]);   // low = even key
            kloT[f * 516 + pw] = cvtpk(lo[1][f], lo[0][f]);
        }
    }
    __syncthreads();

    // ---------------- main loop ----------------
    int lane = tid & 31, warp = tid >> 5;
    int g  = lane >> 2;        // 0..7
    int tc = lane & 3;         // 0..3
    int sw = g & 4;            // swizzle for key-major word loads
    int hiOff = tc ^ sw;
    int loOff = hiOff ^ 4;

    int qbase = qt * 64 + warp * 16;
    int q0 = qbase + g;        // plane-local query indices (q0&4 == g&4)
    int q1 = q0 + 8;

    u32 A0 = skey[q0 * 8 + hiOff];
    u32 A1 = skey[q1 * 8 + hiOff];
    u32 A2 = skey[q0 * 8 + loOff];
    u32 A3 = skey[q1 * 8 + loOff];

    float o0 = 0.f, o1 = 0.f, o2 = 0.f, o3 = 0.f;
    float den0 = 0.f, den1 = 0.f;
    const float kexp = 1.4426950408889634f * 0.35355339059327373f;

    for (int kb = 0; kb < SS; kb += 16) {
        int k1 = kb + g, k2 = kb + 8 + g;
        u32 bh1 = skey[k1 * 8 + hiOff];
        u32 bl1 = skey[k1 * 8 + loOff];
        u32 bh2 = skey[k2 * 8 + hiOff];
        u32 bl2 = skey[k2 * 8 + loOff];

        // scores, exact fp32 dot via hi/lo split
        float d10, d11, d12, d13, d20, d21, d22, d23;
        MMA_BF16(d10, d11, d12, d13, A0, A1, A2, A3, bh1, bh1, 0.f, 0.f, 0.f, 0.f);
        MMA_BF16(d10, d11, d12, d13, A0, A1, A2, A3, bl1, bl1, d10, d11, d12, d13);
        MMA_BF16(d20, d21, d22, d23, A0, A1, A2, A3, bh2, bh2, 0.f, 0.f, 0.f, 0.f);
        MMA_BF16(d20, d21, d22, d23, A0, A1, A2, A3, bl2, bl2, d20, d21, d22, d23);

        // softmax weights
        float w10 = ex2(d10 * kexp), w11 = ex2(d11 * kexp);
        float w12 = ex2(d12 * kexp), w13 = ex2(d13 * kexp);
        float w20 = ex2(d20 * kexp), w21 = ex2(d21 * kexp);
        float w22 = ex2(d22 * kexp), w23 = ex2(d23 * kexp);
        den0 += (w10 + w11) + (w20 + w21);   // row g
        den1 += (w12 + w13) + (w22 + w23);   // row g+8

        // D-fragment -> A-fragment of AV MMA (keys = K dim)
        u32 W0 = cvtpk(w11, w10);   // (q=g,   keys 2tc,2tc+1)
        u32 W1 = cvtpk(w13, w12);   // (q=g+8, keys 2tc,2tc+1)
        u32 W2 = cvtpk(w21, w20);   // (q=g,   keys 8+2tc)
        u32 W3 = cvtpk(w23, w22);   // (q=g+8, keys 8+2tc)

        int cw = kb >> 1;
        u32 Bh0 = khiT[g * 516 + cw + tc];
        u32 Bh1 = khiT[g * 516 + cw + 4 + tc];
        u32 Bl0 = kloT[g * 516 + cw + tc];
        u32 Bl1 = kloT[g * 516 + cw + 4 + tc];

        MMA_BF16(o0, o1, o2, o3, W0, W1, W2, W3, Bh0, Bh1, o0, o1, o2, o3);
        MMA_BF16(o0, o1, o2, o3, W0, W1, W2, W3, Bl0, Bl1, o0, o1, o2, o3);
    }

    // full denominators: reduce over the 4 lanes of the quad (same g)
    den0 += __shfl_xor_sync(0xffffffffu, den0, 1);
    den0 += __shfl_xor_sync(0xffffffffu, den0, 2);
    den1 += __shfl_xor_sync(0xffffffffu, den1, 1);
    den1 += __shfl_xor_sync(0xffffffffu, den1, 2);
    float i0 = __frcp_rn(den0), i1 = __frcp_rn(den1);

    int tok0 = b * SS + q0;
    int tok1 = tok0 + 8;
    float2* o2p = (float2*)g_attn;
    o2p[tok0 * 32 + h * 4 + tc] = make_float2(o0 * i0, o1 * i0);
    o2p[tok1 * 32 + h * 4 + tc] = make_float2(o2 * i1, o3 * i1);
}

// ---------------------------------------------------------------------------
// Kernel 3: out[token, e] = sum_k attn[token, k] * W[e, k] (R5, passing)
// ---------------------------------------------------------------------------
__global__ __launch_bounds__(256) void combine_kernel(const float* __restrict__ W,
                                                      float* __restrict__ out) {
    __shared__ float wt[EE * EE];
    __shared__ float rows[32][68];

    int tid = threadIdx.x;
    for (int i = tid; i < EE * EE; i += 256) {
        int e = i >> 6, k = i & 63;
        wt[k * EE + e] = W[i];
    }
    int token0 = blockIdx.x * 32;
    const float4* ga4 = (const float4*)g_attn + token0 * 16;
    for (int i = tid; i < 512; i += 256) {
        int t = i >> 4, kg = i & 15;
        float4 v = ga4[i];
        rows[t][kg * 4 + 0] = v.x; rows[t][kg * 4 + 1] = v.y;
        rows[t][kg * 4 + 2] = v.z; rows[t][kg * 4 + 3] = v.w;
    }
    __syncthreads();

    int t  = tid >> 3;
    int og = tid & 7;
    const ulonglong2* wt2 = (const ulonglong2*)wt;

    u64 a0 = 0, a1 = 0, a2 = 0, a3 = 0;
#pragma unroll
    for (int k = 0; k < EE; k++) {
        float r = rows[t][k];
        u64 rr = pk2(r, r);
        ulonglong2 b0 = wt2[k * 16 + og * 2 + 0];
        ulonglong2 b1 = wt2[k * 16 + og * 2 + 1];
        a0 = pfma(rr, b0.x, a0);
        a1 = pfma(rr, b0.y, a1);
        a2 = pfma(rr, b1.x, a2);
        a3 = pfma(rr, b1.y, a3);
    }
    ulonglong2* o2 = (ulonglong2*)out;
    int token = token0 + t;
    ulonglong2 r0; r0.x = a0; r0.y = a1;
    ulonglong2 r1; r1.x = a2; r1.y = a3;
    o2[token * 16 + og * 2 + 0] = r0;
    o2[token * 16 + og * 2 + 1] = r1;
}

// ---------------------------------------------------------------------------
extern "C" void kernel_launch(void* const* d_in, const int* in_sizes, int n_in,
                              void* d_out, int out_size) {
    const float* x      = (const float*)d_in[0];   // [8,1024,64]
    const float* theta  = (const float*)d_in[1];   // [8]
    const float* Wc     = (const float*)d_in[2];   // [64,64]
    float* out          = (float*)d_out;           // [8,1024,64]

    cudaFuncSetAttribute(attn_fused, cudaFuncAttributeMaxDynamicSharedMemorySize,
                         ATTN_SMEM_BYTES);

    dim3 agrid(NBH, SS / 64);
    attn_fused<<<agrid, 128, ATTN_SMEM_BYTES>>>(x, theta);

    combine_kernel<<<NTOK / 32, 256>>>(Wc, out);
}

// round 8
// speedup vs baseline: 2.0183x; 1.1096x over previous
#include <cuda_runtime.h>
#include <cuda_bf16.h>

#define BB 8
#define SS 1024
#define HH 8
#define EE 64
#define NBH (BB*HH)
#define NTOK (BB*SS)

typedef unsigned long long u64;
typedef unsigned int u32;

__device__ __align__(16) float g_attn[NTOK * EE];   // 2 MB scratch

// ---------------------------------------------------------------------------
// helpers
// ---------------------------------------------------------------------------
__device__ __forceinline__ u64 pk2(float lo, float hi) {
    u64 r; asm("mov.b64 %0, {%1, %2};" : "=l"(r) : "f"(lo), "f"(hi)); return r;
}
__device__ __forceinline__ u64 pfma(u64 a, u64 b, u64 c) {
    u64 d; asm("fma.rn.f32x2 %0, %1, %2, %3;" : "=l"(d) : "l"(a), "l"(b), "l"(c)); return d;
}
__device__ __forceinline__ float ex2(float x) {
    float y; asm("ex2.approx.f32 %0, %1;" : "=f"(y) : "f"(x)); return y;
}
// pack two fp32 -> bf16x2; first arg lands in HIGH half, second in LOW half
__device__ __forceinline__ u32 cvtpk(float hi, float lo) {
    u32 r; asm("cvt.rn.bf16x2.f32 %0, %1, %2;" : "=r"(r) : "f"(hi), "f"(lo)); return r;
}
// bf16x2 halves back to fp32 (bf16->f32 is a 16-bit shift)
__device__ __forceinline__ float bflo_f(u32 w) { return __uint_as_float(w << 16); }
__device__ __forceinline__ float bfhi_f(u32 w) { return __uint_as_float(w & 0xffff0000u); }

// m16n8k16 row.col bf16 MMA, fp32 accum (HMMA fallback path, sm_80+ PTX)
#define MMA_BF16(d0,d1,d2,d3, a0,a1,a2,a3, b0,b1, c0,c1,c2,c3) \
  asm volatile("mma.sync.aligned.m16n8k16.row.col.f32.bf16.bf16.f32 " \
    "{%0,%1,%2,%3}, {%4,%5,%6,%7}, {%8,%9}, {%10,%11,%12,%13};" \
    : "=f"(d0),"=f"(d1),"=f"(d2),"=f"(d3) \
    : "r"(a0),"r"(a1),"r"(a2),"r"(a3), "r"(b0),"r"(b1), \
      "f"(c0),"f"(c1),"f"(c2),"f"(c3))

// ---------------------------------------------------------------------------
// Fused proj + attention. CTA = (bh, qtile of 256 queries), 512 threads.
// Same layouts as R7 (passing), 4x the warps per smem image:
//   skey (key-major, word idx XOR (key&4)):   [1024][8] u32
//   khiT/kloT (feature-major, stride 516):    [8][516] u32
// Softmax weights now hi/lo split (3 AV MMAs): numerator exact to ~2e-5.
// ---------------------------------------------------------------------------
#define ATTN_SMEM_BYTES 65792   // (8192 + 4128 + 4128) u32

__global__ __launch_bounds__(512, 2) void attn_fused(const float* __restrict__ x,
                                                     const float* __restrict__ theta) {
    extern __shared__ __align__(16) u32 sm[];
    u32* skey = sm;                 // [1024*8]
    u32* khiT = sm + 8192;          // [8*516]
    u32* kloT = sm + 8192 + 4128;   // [8*516]

    int bh = blockIdx.x;
    int b = bh >> 3, h = bh & 7;
    int qt = blockIdx.y;
    int tid = threadIdx.x;

    float th[8];
#pragma unroll
    for (int i = 0; i < 8; i++) th[i] = __ldg(&theta[i]);

    // ---------------- build phase: keys 2*tid, 2*tid+1 ----------------
    const float* xb = x + (size_t)(b * SS) * 64 + h * 8;
    {
        float hi[2][8], lo[2][8];
#pragma unroll
        for (int j = 0; j < 2; j++) {
            int s = tid * 2 + j;
            const float4* xs = (const float4*)(xb + (size_t)s * 64);
            float4 v0 = xs[0], v1 = xs[1];
            float a[8] = {v0.x, v0.y, v0.z, v0.w, v1.x, v1.y, v1.z, v1.w};
            float c[8];
#pragma unroll
            for (int i = 0; i < 8; i++) c[i] = __cosf(a[i] + th[i]);
            float p[8];
            p[1] = c[0] * c[1];
#pragma unroll
            for (int w = 2; w < 8; w++) p[w] = p[w - 1] * c[w];
            float qq = c[1];
#pragma unroll
            for (int i = 2; i < 8; i++) qq *= c[i];
            p[0] = qq;
#pragma unroll
            for (int i = 0; i < 8; i++) {
                float hf = __bfloat162float(__float2bfloat16(p[i]));
                hi[j][i] = hf;
                lo[j][i] = p[i] - hf;
            }
            uint4 HW = make_uint4(cvtpk(hi[j][1], hi[j][0]), cvtpk(hi[j][3], hi[j][2]),
                                  cvtpk(hi[j][5], hi[j][4]), cvtpk(hi[j][7], hi[j][6]));
            uint4 LW = make_uint4(cvtpk(lo[j][1], lo[j][0]), cvtpk(lo[j][3], lo[j][2]),
                                  cvtpk(lo[j][5], lo[j][4]), cvtpk(lo[j][7], lo[j][6]));
            uint4* kp = (uint4*)(skey + s * 8);
            if (s & 4) { kp[0] = LW; kp[1] = HW; }   // word index XOR 4
            else       { kp[0] = HW; kp[1] = LW; }
        }
        int pw = tid;   // key pair index
#pragma unroll
        for (int f = 0; f < 8; f++) {
            khiT[f * 516 + pw] = cvtpk(hi[1][f], hi[0][f]);   // low half = even key
            kloT[f * 516 + pw] = cvtpk(lo[1][f], lo[0][f]);
        }
    }
    __syncthreads();

    // ---------------- main loop: warp = 16 queries ----------------
    int lane = tid & 31, warp = tid >> 5;
    int g  = lane >> 2;        // 0..7
    int tc = lane & 3;         // 0..3
    int sw = g & 4;
    int hiOff = tc ^ sw;
    int loOff = hiOff ^ 4;

    int qbase = qt * 256 + warp * 16;
    int q0 = qbase + g;        // q0&4 == g&4 (qbase multiple of 16)
    int q1 = q0 + 8;

    u32 A0 = skey[q0 * 8 + hiOff];
    u32 A1 = skey[q1 * 8 + hiOff];
    u32 A2 = skey[q0 * 8 + loOff];
    u32 A3 = skey[q1 * 8 + loOff];

    float o0 = 0.f, o1 = 0.f, o2 = 0.f, o3 = 0.f;
    float den0 = 0.f, den1 = 0.f;
    const float kexp = 1.4426950408889634f * 0.35355339059327373f;

    for (int kb = 0; kb < SS; kb += 16) {
        int k1 = kb + g, k2 = kb + 8 + g;   // k&4 == g&4
        u32 bh1 = skey[k1 * 8 + hiOff];
        u32 bl1 = skey[k1 * 8 + loOff];
        u32 bh2 = skey[k2 * 8 + hiOff];
        u32 bl2 = skey[k2 * 8 + loOff];

        // scores, exact fp32 dot via hi/lo split
        float d10, d11, d12, d13, d20, d21, d22, d23;
        MMA_BF16(d10, d11, d12, d13, A0, A1, A2, A3, bh1, bh1, 0.f, 0.f, 0.f, 0.f);
        MMA_BF16(d10, d11, d12, d13, A0, A1, A2, A3, bl1, bl1, d10, d11, d12, d13);
        MMA_BF16(d20, d21, d22, d23, A0, A1, A2, A3, bh2, bh2, 0.f, 0.f, 0.f, 0.f);
        MMA_BF16(d20, d21, d22, d23, A0, A1, A2, A3, bl2, bl2, d20, d21, d22, d23);

        // softmax weights (fp32)
        float w10 = ex2(d10 * kexp), w11 = ex2(d11 * kexp);
        float w12 = ex2(d12 * kexp), w13 = ex2(d13 * kexp);
        float w20 = ex2(d20 * kexp), w21 = ex2(d21 * kexp);
        float w22 = ex2(d22 * kexp), w23 = ex2(d23 * kexp);
        den0 += (w10 + w11) + (w20 + w21);   // row g
        den1 += (w12 + w13) + (w22 + w23);   // row g+8

        // weight hi words (A-fragment of AV MMA)
        u32 W0 = cvtpk(w11, w10);
        u32 W1 = cvtpk(w13, w12);
        u32 W2 = cvtpk(w21, w20);
        u32 W3 = cvtpk(w23, w22);
        // weight lo words (residuals, ~4e-3 of w)
        u32 L0 = cvtpk(w11 - bfhi_f(W0), w10 - bflo_f(W0));
        u32 L1 = cvtpk(w13 - bfhi_f(W1), w12 - bflo_f(W1));
        u32 L2 = cvtpk(w21 - bfhi_f(W2), w20 - bflo_f(W2));
        u32 L3 = cvtpk(w23 - bfhi_f(W3), w22 - bflo_f(W3));

        int cw = kb >> 1;
        u32 Bh0 = khiT[g * 516 + cw + tc];
        u32 Bh1 = khiT[g * 516 + cw + 4 + tc];
        u32 Bl0 = kloT[g * 516 + cw + tc];
        u32 Bl1 = kloT[g * 516 + cw + 4 + tc];

        MMA_BF16(o0, o1, o2, o3, W0, W1, W2, W3, Bh0, Bh1, o0, o1, o2, o3);
        MMA_BF16(o0, o1, o2, o3, W0, W1, W2, W3, Bl0, Bl1, o0, o1, o2, o3);
        MMA_BF16(o0, o1, o2, o3, L0, L1, L2, L3, Bh0, Bh1, o0, o1, o2, o3);
    }

    // full denominators: reduce over the quad (same g)
    den0 += __shfl_xor_sync(0xffffffffu, den0, 1);
    den0 += __shfl_xor_sync(0xffffffffu, den0, 2);
    den1 += __shfl_xor_sync(0xffffffffu, den1, 1);
    den1 += __shfl_xor_sync(0xffffffffu, den1, 2);
    float i0 = __frcp_rn(den0), i1 = __frcp_rn(den1);

    int tok0 = b * SS + q0;
    int tok1 = tok0 + 8;
    float2* o2p = (float2*)g_attn;
    o2p[tok0 * 32 + h * 4 + tc] = make_float2(o0 * i0, o1 * i0);
    o2p[tok1 * 32 + h * 4 + tc] = make_float2(o2 * i1, o3 * i1);
}

// ---------------------------------------------------------------------------
// Kernel 3: out[token, e] = sum_k attn[token, k] * W[e, k]
// 512 CTAs x 256 thr = 16 tokens x 16 e-quads (4 outputs/thread).
// Per k: 1 broadcast LDS.32 + 1 LDS.128 + 2 FFMA2.
// ---------------------------------------------------------------------------
__global__ __launch_bounds__(256) void combine_kernel(const float* __restrict__ W,
                                                      float* __restrict__ out) {
    __shared__ float wt[EE * EE];        // wt[k*64+e] = W[e*64+k], 16 KB
    __shared__ float rows[16][68];       // 16 token rows, padded

    int tid = threadIdx.x;
    for (int i = tid; i < EE * EE; i += 256) {
        int e = i >> 6, k = i & 63;
        wt[k * EE + e] = W[i];
    }
    int token0 = blockIdx.x * 16;
    const float4* ga4 = (const float4*)g_attn + token0 * 16;
    {
        int i = tid;                      // 16 tokens x 16 float4 = 256
        int t = i >> 4, kg = i & 15;
        float4 v = ga4[i];
        rows[t][kg * 4 + 0] = v.x; rows[t][kg * 4 + 1] = v.y;
        rows[t][kg * 4 + 2] = v.z; rows[t][kg * 4 + 3] = v.w;
    }
    __syncthreads();

    int t  = tid >> 4;     // token 0..15
    int og = tid & 15;     // e-quad: outputs og*4 .. og*4+3
    const ulonglong2* wt2 = (const ulonglong2*)wt;   // wt2[k*16 + og]

    u64 a0 = 0, a1 = 0;
#pragma unroll
    for (int k = 0; k < EE; k++) {
        float r = rows[t][k];
        u64 rr = pk2(r, r);
        ulonglong2 bw = wt2[k * 16 + og];
        a0 = pfma(rr, bw.x, a0);
        a1 = pfma(rr, bw.y, a1);
    }
    ulonglong2* o2 = (ulonglong2*)out;
    int token = token0 + t;
    ulonglong2 r0; r0.x = a0; r0.y = a1;
    o2[token * 16 + og] = r0;
}

// ---------------------------------------------------------------------------
extern "C" void kernel_launch(void* const* d_in, const int* in_sizes, int n_in,
                              void* d_out, int out_size) {
    const float* x      = (const float*)d_in[0];   // [8,1024,64]
    const float* theta  = (const float*)d_in[1];   // [8]
    const float* Wc     = (const float*)d_in[2];   // [64,64]
    float* out          = (float*)d_out;           // [8,1024,64]

    cudaFuncSetAttribute(attn_fused, cudaFuncAttributeMaxDynamicSharedMemorySize,
                         ATTN_SMEM_BYTES);

    dim3 agrid(NBH, SS / 256);
    attn_fused<<<agrid, 512, ATTN_SMEM_BYTES>>>(x, theta);

    combine_kernel<<<NTOK / 16, 256>>>(Wc, out);
}

// round 9
// speedup vs baseline: 2.3779x; 1.1782x over previous
#include <cuda_runtime.h>
#include <cuda_bf16.h>

#define BB 8
#define SS 1024
#define HH 8
#define EE 64
#define NBH (BB*HH)
#define NTOK (BB*SS)

typedef unsigned long long u64;
typedef unsigned int u32;

__device__ __align__(16) float g_attn[NTOK * EE];   // 2 MB scratch

// ---------------------------------------------------------------------------
// helpers
// ---------------------------------------------------------------------------
__device__ __forceinline__ u64 pk2(float lo, float hi) {
    u64 r; asm("mov.b64 %0, {%1, %2};" : "=l"(r) : "f"(lo), "f"(hi)); return r;
}
__device__ __forceinline__ u64 pfma(u64 a, u64 b, u64 c) {
    u64 d; asm("fma.rn.f32x2 %0, %1, %2, %3;" : "=l"(d) : "l"(a), "l"(b), "l"(c)); return d;
}
__device__ __forceinline__ float ex2(float x) {
    float y; asm("ex2.approx.f32 %0, %1;" : "=f"(y) : "f"(x)); return y;
}
// pack two fp32 -> bf16x2; first arg lands in HIGH half, second in LOW half
__device__ __forceinline__ u32 cvtpk(float hi, float lo) {
    u32 r; asm("cvt.rn.bf16x2.f32 %0, %1, %2;" : "=r"(r) : "f"(hi), "f"(lo)); return r;
}
// bf16x2 halves back to fp32 (bf16->f32 is a 16-bit shift)
__device__ __forceinline__ float bflo_f(u32 w) { return __uint_as_float(w << 16); }
__device__ __forceinline__ float bfhi_f(u32 w) { return __uint_as_float(w & 0xffff0000u); }
__device__ __forceinline__ float bfrnd(float v) {
    return __bfloat162float(__float2bfloat16(v));
}

// m16n8k16 row.col bf16 MMA, fp32 accum (HMMA fallback path, sm_80+ PTX)
#define MMA_BF16(d0,d1,d2,d3, a0,a1,a2,a3, b0,b1, c0,c1,c2,c3) \
  asm volatile("mma.sync.aligned.m16n8k16.row.col.f32.bf16.bf16.f32 " \
    "{%0,%1,%2,%3}, {%4,%5,%6,%7}, {%8,%9}, {%10,%11,%12,%13};" \
    : "=f"(d0),"=f"(d1),"=f"(d2),"=f"(d3) \
    : "r"(a0),"r"(a1),"r"(a2),"r"(a3), "r"(b0),"r"(b1), \
      "f"(c0),"f"(c1),"f"(c2),"f"(c3))

// ---------------------------------------------------------------------------
// Fused proj + attention. CTA = (bh, qtile of 256 queries), 512 threads.
//   skey (key-major, word idx XOR (key&4)):   [1024][8] u32
//   khiT/kloT (feature-major, stride 516):    [8][516] u32
// softmax scale folded into A-fragments at load (re-split hi/lo after scale),
// weights hi/lo split (3 AV MMAs): numerator exact to ~2e-5.
// ---------------------------------------------------------------------------
#define ATTN_SMEM_BYTES 65792   // (8192 + 4128 + 4128) u32

__global__ __launch_bounds__(512, 2) void attn_fused(const float* __restrict__ x,
                                                     const float* __restrict__ theta) {
    extern __shared__ __align__(16) u32 sm[];
    u32* skey = sm;                 // [1024*8]
    u32* khiT = sm + 8192;          // [8*516]
    u32* kloT = sm + 8192 + 4128;   // [8*516]

    int bh = blockIdx.x;
    int b = bh >> 3, h = bh & 7;
    int qt = blockIdx.y;
    int tid = threadIdx.x;

    float th[8];
#pragma unroll
    for (int i = 0; i < 8; i++) th[i] = __ldg(&theta[i]);

    // ---------------- build phase: keys 2*tid, 2*tid+1 ----------------
    const float* xb = x + (size_t)(b * SS) * 64 + h * 8;
    {
        float hi[2][8], lo[2][8];
#pragma unroll
        for (int j = 0; j < 2; j++) {
            int s = tid * 2 + j;
            const float4* xs = (const float4*)(xb + (size_t)s * 64);
            float4 v0 = xs[0], v1 = xs[1];
            float a[8] = {v0.x, v0.y, v0.z, v0.w, v1.x, v1.y, v1.z, v1.w};
            float c[8];
#pragma unroll
            for (int i = 0; i < 8; i++) c[i] = __cosf(a[i] + th[i]);
            float p[8];
            p[1] = c[0] * c[1];
#pragma unroll
            for (int w = 2; w < 8; w++) p[w] = p[w - 1] * c[w];
            float qq = c[1];
#pragma unroll
            for (int i = 2; i < 8; i++) qq *= c[i];
            p[0] = qq;
#pragma unroll
            for (int i = 0; i < 8; i++) {
                float hf = bfrnd(p[i]);
                hi[j][i] = hf;
                lo[j][i] = p[i] - hf;
            }
            uint4 HW = make_uint4(cvtpk(hi[j][1], hi[j][0]), cvtpk(hi[j][3], hi[j][2]),
                                  cvtpk(hi[j][5], hi[j][4]), cvtpk(hi[j][7], hi[j][6]));
            uint4 LW = make_uint4(cvtpk(lo[j][1], lo[j][0]), cvtpk(lo[j][3], lo[j][2]),
                                  cvtpk(lo[j][5], lo[j][4]), cvtpk(lo[j][7], lo[j][6]));
            uint4* kp = (uint4*)(skey + s * 8);
            if (s & 4) { kp[0] = LW; kp[1] = HW; }   // word index XOR 4
            else       { kp[0] = HW; kp[1] = LW; }
        }
        int pw = tid;
#pragma unroll
        for (int f = 0; f < 8; f++) {
            khiT[f * 516 + pw] = cvtpk(hi[1][f], hi[0][f]);   // low half = even key
            kloT[f * 516 + pw] = cvtpk(lo[1][f], lo[0][f]);
        }
    }
    __syncthreads();

    // ---------------- main loop: warp = 16 queries ----------------
    int lane = tid & 31, warp = tid >> 5;
    int g  = lane >> 2;        // 0..7
    int tc = lane & 3;         // 0..3
    int sw = g & 4;
    int hiOff = tc ^ sw;
    int loOff = hiOff ^ 4;

    int qbase = qt * 256 + warp * 16;
    int q0 = qbase + g;        // q0&4 == g&4
    int q1 = q0 + 8;

    // A-fragments with softmax scale folded in: s = kexp*(qhi+qlo), re-split
    const float kexp = 1.4426950408889634f * 0.35355339059327373f;
    u32 A0, A1, A2, A3;
    {
        u32 h0 = skey[q0 * 8 + hiOff], l0 = skey[q0 * 8 + loOff];
        u32 h1 = skey[q1 * 8 + hiOff], l1 = skey[q1 * 8 + loOff];
        float f0 = (bflo_f(h0) + bflo_f(l0)) * kexp;
        float f1 = (bfhi_f(h0) + bfhi_f(l0)) * kexp;
        float g0 = (bflo_f(h1) + bflo_f(l1)) * kexp;
        float g1 = (bfhi_f(h1) + bfhi_f(l1)) * kexp;
        float f0h = bfrnd(f0), f1h = bfrnd(f1);
        float g0h = bfrnd(g0), g1h = bfrnd(g1);
        A0 = cvtpk(f1h, f0h);
        A1 = cvtpk(g1h, g0h);
        A2 = cvtpk(f1 - f1h, f0 - f0h);
        A3 = cvtpk(g1 - g1h, g0 - g0h);
    }

    float o0 = 0.f, o1 = 0.f, o2 = 0.f, o3 = 0.f;
    float den0 = 0.f, den1 = 0.f;

#pragma unroll 2
    for (int kb = 0; kb < SS; kb += 16) {
        int k1 = kb + g, k2 = kb + 8 + g;   // k&4 == g&4
        u32 bh1 = skey[k1 * 8 + hiOff];
        u32 bl1 = skey[k1 * 8 + loOff];
        u32 bh2 = skey[k2 * 8 + hiOff];
        u32 bl2 = skey[k2 * 8 + loOff];

        // scores (scale already folded into A): exact fp32 dot via hi/lo split
        float d10, d11, d12, d13, d20, d21, d22, d23;
        MMA_BF16(d10, d11, d12, d13, A0, A1, A2, A3, bh1, bh1, 0.f, 0.f, 0.f, 0.f);
        MMA_BF16(d10, d11, d12, d13, A0, A1, A2, A3, bl1, bl1, d10, d11, d12, d13);
        MMA_BF16(d20, d21, d22, d23, A0, A1, A2, A3, bh2, bh2, 0.f, 0.f, 0.f, 0.f);
        MMA_BF16(d20, d21, d22, d23, A0, A1, A2, A3, bl2, bl2, d20, d21, d22, d23);

        // softmax weights straight off the MMA output
        float w10 = ex2(d10), w11 = ex2(d11);
        float w12 = ex2(d12), w13 = ex2(d13);
        float w20 = ex2(d20), w21 = ex2(d21);
        float w22 = ex2(d22), w23 = ex2(d23);
        den0 += (w10 + w11) + (w20 + w21);   // row g
        den1 += (w12 + w13) + (w22 + w23);   // row g+8

        u32 W0 = cvtpk(w11, w10);
        u32 W1 = cvtpk(w13, w12);
        u32 W2 = cvtpk(w21, w20);
        u32 W3 = cvtpk(w23, w22);
        u32 L0 = cvtpk(w11 - bfhi_f(W0), w10 - bflo_f(W0));
        u32 L1 = cvtpk(w13 - bfhi_f(W1), w12 - bflo_f(W1));
        u32 L2 = cvtpk(w21 - bfhi_f(W2), w20 - bflo_f(W2));
        u32 L3 = cvtpk(w23 - bfhi_f(W3), w22 - bflo_f(W3));

        int cw = kb >> 1;
        u32 Bh0 = khiT[g * 516 + cw + tc];
        u32 Bh1 = khiT[g * 516 + cw + 4 + tc];
        u32 Bl0 = kloT[g * 516 + cw + tc];
        u32 Bl1 = kloT[g * 516 + cw + 4 + tc];

        MMA_BF16(o0, o1, o2, o3, W0, W1, W2, W3, Bh0, Bh1, o0, o1, o2, o3);
        MMA_BF16(o0, o1, o2, o3, W0, W1, W2, W3, Bl0, Bl1, o0, o1, o2, o3);
        MMA_BF16(o0, o1, o2, o3, L0, L1, L2, L3, Bh0, Bh1, o0, o1, o2, o3);
    }

    // full denominators: reduce over the quad (same g)
    den0 += __shfl_xor_sync(0xffffffffu, den0, 1);
    den0 += __shfl_xor_sync(0xffffffffu, den0, 2);
    den1 += __shfl_xor_sync(0xffffffffu, den1, 1);
    den1 += __shfl_xor_sync(0xffffffffu, den1, 2);
    float i0 = __frcp_rn(den0), i1 = __frcp_rn(den1);

    int tok0 = b * SS + q0;
    int tok1 = tok0 + 8;
    float2* o2p = (float2*)g_attn;
    o2p[tok0 * 32 + h * 4 + tc] = make_float2(o0 * i0, o1 * i0);
    o2p[tok1 * 32 + h * 4 + tc] = make_float2(o2 * i1, o3 * i1);
}

// ---------------------------------------------------------------------------
// Kernel 3: out[token, e] = sum_k attn[token, k] * W[e, k]
// 512 CTAs x 256 thr = 16 tokens x 16 e-quads.
// Transpose fill: coalesced gmem read, rows padded to 68 floats ->
// STS conflicts 32-way -> 4-way; main-loop LDS.128 reads conflict-free.
// ---------------------------------------------------------------------------
__global__ __launch_bounds__(256) void combine_kernel(const float* __restrict__ W,
                                                      float* __restrict__ out) {
    __shared__ float wt[EE * 68];        // wt[k*68+e] = W[e*64+k], padded rows
    __shared__ float rows[16][68];       // 16 token rows, padded

    int tid = threadIdx.x;
    for (int i = tid; i < EE * EE; i += 256) {
        int k = i & 63, e = i >> 6;          // coalesced read of W row e
        wt[k * 68 + e] = W[e * 64 + k];      // 4-way STS (4k mod 32)
    }
    int token0 = blockIdx.x * 16;
    const float4* ga4 = (const float4*)g_attn + token0 * 16;
    {
        int i = tid;                         // 16 tokens x 16 float4 = 256
        int t = i >> 4, kg = i & 15;
        float4 v = ga4[i];
        rows[t][kg * 4 + 0] = v.x; rows[t][kg * 4 + 1] = v.y;
        rows[t][kg * 4 + 2] = v.z; rows[t][kg * 4 + 3] = v.w;
    }
    __syncthreads();

    int t  = tid >> 4;     // token 0..15
    int og = tid & 15;     // e-quad: outputs og*4 .. og*4+3
    const ulonglong2* wt2 = (const ulonglong2*)wt;   // 17 16B-units per row

    u64 a0 = 0, a1 = 0;
#pragma unroll
    for (int k = 0; k < EE; k++) {
        float r = rows[t][k];
        u64 rr = pk2(r, r);
        ulonglong2 bw = wt2[k * 17 + og];
        a0 = pfma(rr, bw.x, a0);
        a1 = pfma(rr, bw.y, a1);
    }
    ulonglong2* o2 = (ulonglong2*)out;
    int token = token0 + t;
    ulonglong2 r0; r0.x = a0; r0.y = a1;
    o2[token * 16 + og] = r0;
}

// ---------------------------------------------------------------------------
extern "C" void kernel_launch(void* const* d_in, const int* in_sizes, int n_in,
                              void* d_out, int out_size) {
    const float* x      = (const float*)d_in[0];   // [8,1024,64]
    const float* theta  = (const float*)d_in[1];   // [8]
    const float* Wc     = (const float*)d_in[2];   // [64,64]
    float* out          = (float*)d_out;           // [8,1024,64]

    cudaFuncSetAttribute(attn_fused, cudaFuncAttributeMaxDynamicSharedMemorySize,
                         ATTN_SMEM_BYTES);

    dim3 agrid(NBH, SS / 256);
    attn_fused<<<agrid, 512, ATTN_SMEM_BYTES>>>(x, theta);

    combine_kernel<<<NTOK / 16, 256>>>(Wc, out);
}